// round 7
// baseline (speedup 1.0000x reference)
#include <cuda_runtime.h>

// ---------------------------------------------------------------------------
// Problem constants
// ---------------------------------------------------------------------------
#define DIM   1024         // model dim D
#define SEQ   1024         // SS == ST
#define BATCH 4
#define NH    16
#define HDIM  64
#define FFD   4096
#define NL    6
#define MROWS (BATCH * SEQ)   // 4096
#define VOCAB 32000

// ---------------------------------------------------------------------------
// Scratch (static device globals -- no allocation allowed)
// ---------------------------------------------------------------------------
__device__ float g_x [MROWS * DIM];          // encoder activations
__device__ float g_y [MROWS * DIM];          // decoder activations
__device__ float g_q [MROWS * DIM];          // Q / attention-out reuse
__device__ float g_k [MROWS * DIM];
__device__ float g_v [MROWS * DIM];
__device__ float g_t [MROWS * DIM];          // sublayer output (pre-LN)
__device__ float g_ff[MROWS * FFD];          // FF intermediate
__device__ float g_sc[(size_t)BATCH * NH * SEQ * SEQ];   // attention scores (268 MB)

// ---------------------------------------------------------------------------
// Embedding + sinusoidal positional encoding
// grid = MROWS blocks, 256 threads
// ---------------------------------------------------------------------------
__global__ __launch_bounds__(256)
void embed_kernel(const int* __restrict__ tok, const float* __restrict__ emb,
                  float* __restrict__ out)
{
    int bs = blockIdx.x;
    int s  = bs & (SEQ - 1);
    int t  = tok[bs];
    const float* e = emb + (size_t)t * DIM;
    float* o = out + (size_t)bs * DIM;
    const float c = (float)(-9.210340371976184 / 1024.0);   // -ln(10000)/D
#pragma unroll
    for (int i = 0; i < 4; i++) {
        int d  = threadIdx.x + i * 256;
        int i2 = d & ~1;
        float div = expf((float)i2 * c);
        float ang = (float)s * div;
        float pe  = (d & 1) ? cosf(ang) : sinf(ang);
        o[d] = e[d] + pe;
    }
}

// ---------------------------------------------------------------------------
// SGEMM: C[M,N] = A[M,K] @ B[K,N] + bias[N]   (optional ReLU)
// Requires M%128==0, N%128==0, K%8==0 (true for all call sites).
// 128x128 block tile, BK=8, 256 threads, 8x8 per thread (2x2 split warp tile).
// ---------------------------------------------------------------------------
__global__ __launch_bounds__(256, 2)
void sgemm_kernel(const float* __restrict__ A, const float* __restrict__ B,
                  const float* __restrict__ bias, float* __restrict__ C,
                  int M, int N, int K, int relu)
{
    __shared__ __align__(16) float As[8][128];
    __shared__ __align__(16) float Bs[8][128];

    const int tid  = threadIdx.x;
    const int brow = blockIdx.y << 7;
    const int bcol = blockIdx.x << 7;
    const int tx   = tid & 15;
    const int ty   = tid >> 4;

    const int a_row = tid >> 1;
    const int a_col = (tid & 1) << 2;
    const int b_row = tid >> 5;
    const int b_col = (tid & 31) << 2;

    const float* Ap = A + (size_t)(brow + a_row) * K + a_col;
    const float* Bp = B + (size_t)b_row * N + bcol + b_col;

    float acc[8][8];
#pragma unroll
    for (int i = 0; i < 8; i++)
#pragma unroll
        for (int j = 0; j < 8; j++) acc[i][j] = 0.f;

    for (int k0 = 0; k0 < K; k0 += 8) {
        float4 av = *(const float4*)Ap;
        float4 bv = *(const float4*)Bp;
        As[a_col + 0][a_row] = av.x;
        As[a_col + 1][a_row] = av.y;
        As[a_col + 2][a_row] = av.z;
        As[a_col + 3][a_row] = av.w;
        *(float4*)&Bs[b_row][b_col] = bv;
        __syncthreads();
#pragma unroll
        for (int kk = 0; kk < 8; kk++) {
            float4 a0 = *(const float4*)&As[kk][ty * 4];
            float4 a1 = *(const float4*)&As[kk][ty * 4 + 64];
            float4 b0 = *(const float4*)&Bs[kk][tx * 4];
            float4 b1 = *(const float4*)&Bs[kk][tx * 4 + 64];
            float ar[8] = {a0.x, a0.y, a0.z, a0.w, a1.x, a1.y, a1.z, a1.w};
            float br[8] = {b0.x, b0.y, b0.z, b0.w, b1.x, b1.y, b1.z, b1.w};
#pragma unroll
            for (int i = 0; i < 8; i++)
#pragma unroll
                for (int j = 0; j < 8; j++)
                    acc[i][j] = fmaf(ar[i], br[j], acc[i][j]);
        }
        __syncthreads();
        Ap += 8;
        Bp += (size_t)8 * N;
    }

#pragma unroll
    for (int i = 0; i < 8; i++) {
        int row = brow + ((i < 4) ? (ty * 4 + i) : (64 + ty * 4 + (i - 4)));
#pragma unroll
        for (int jh = 0; jh < 2; jh++) {
            int col = bcol + jh * 64 + tx * 4;
            float4 bb = *(const float4*)&bias[col];
            float4 r;
            r.x = acc[i][jh * 4 + 0] + bb.x;
            r.y = acc[i][jh * 4 + 1] + bb.y;
            r.z = acc[i][jh * 4 + 2] + bb.z;
            r.w = acc[i][jh * 4 + 3] + bb.w;
            if (relu) {
                r.x = fmaxf(r.x, 0.f); r.y = fmaxf(r.y, 0.f);
                r.z = fmaxf(r.z, 0.f); r.w = fmaxf(r.w, 0.f);
            }
            *(float4*)&C[(size_t)row * N + col] = r;
        }
    }
}

// ---------------------------------------------------------------------------
// Attention scores: sc[bh, q, k] = dot(Q[b,q,h,:], K[b,k,h,:]) / 8, masked.
// causal==0: mask k where tok[b,k]==0 (src pad mask)
// causal==1: mask unless tok[b,q]!=0 && k<=q      (trg pad & causal)
// grid = (SEQ/64, SEQ/64, B*NH), 256 threads; 64x64 tile, 4x4 per thread.
// ---------------------------------------------------------------------------
__global__ __launch_bounds__(256)
void attn_scores_kernel(const float* __restrict__ Q, const float* __restrict__ Km,
                        const int* __restrict__ tok, float* __restrict__ sc,
                        int causal)
{
    __shared__ __align__(16) float Qs[64][68];
    __shared__ __align__(16) float Ks[64][68];

    int bh = blockIdx.z;
    int b  = bh >> 4, h = bh & 15;
    int q0 = blockIdx.y << 6, k0 = blockIdx.x << 6;
    int tid = threadIdx.x;

    const float* Qb = Q  + ((size_t)(b * SEQ + q0) * NH + h) * HDIM;
    const float* Kb = Km + ((size_t)(b * SEQ + k0) * NH + h) * HDIM;

#pragma unroll
    for (int it = 0; it < 4; it++) {
        int idx = tid + it * 256;
        int r = idx >> 4, c = (idx & 15) << 2;
        *(float4*)&Qs[r][c] = *(const float4*)(Qb + (size_t)r * DIM + c);
        *(float4*)&Ks[r][c] = *(const float4*)(Kb + (size_t)r * DIM + c);
    }
    __syncthreads();

    int tx = tid & 15, ty = tid >> 4;
    float acc[4][4] = {};
#pragma unroll 4
    for (int d0 = 0; d0 < 64; d0 += 4) {
        float4 qv[4], kv[4];
#pragma unroll
        for (int i = 0; i < 4; i++) qv[i] = *(const float4*)&Qs[ty * 4 + i][d0];
#pragma unroll
        for (int j = 0; j < 4; j++) kv[j] = *(const float4*)&Ks[tx + 16 * j][d0];
#pragma unroll
        for (int i = 0; i < 4; i++)
#pragma unroll
            for (int j = 0; j < 4; j++)
                acc[i][j] += qv[i].x * kv[j].x + qv[i].y * kv[j].y
                           + qv[i].z * kv[j].z + qv[i].w * kv[j].w;
    }

    const float scale = 0.125f;   // 1/sqrt(64)
    size_t sbase = (size_t)bh * SEQ * SEQ;
    int qok[4];
#pragma unroll
    for (int i = 0; i < 4; i++)
        qok[i] = causal ? (tok[b * SEQ + q0 + ty * 4 + i] != 0) : 1;
#pragma unroll
    for (int j = 0; j < 4; j++) {
        int k = k0 + tx + 16 * j;
        int kok = causal ? 1 : (tok[b * SEQ + k] != 0);
#pragma unroll
        for (int i = 0; i < 4; i++) {
            int q = q0 + ty * 4 + i;
            int ok = causal ? (qok[i] && (k <= q)) : kok;
            sc[sbase + (size_t)q * SEQ + k] = ok ? acc[i][j] * scale : -1e9f;
        }
    }
}

// ---------------------------------------------------------------------------
// Row softmax (in place). grid = B*NH*SEQ blocks, 256 threads, row len 1024.
// ---------------------------------------------------------------------------
__global__ __launch_bounds__(256)
void softmax_kernel(float* __restrict__ sc)
{
    __shared__ float red[9];
    size_t base = (size_t)blockIdx.x * SEQ;
    int tid = threadIdx.x;

    float v[4];
    float mx = -3.4e38f;
#pragma unroll
    for (int i = 0; i < 4; i++) {
        v[i] = sc[base + tid + i * 256];
        mx = fmaxf(mx, v[i]);
    }
    for (int o = 16; o; o >>= 1) mx = fmaxf(mx, __shfl_xor_sync(0xffffffffu, mx, o));
    if ((tid & 31) == 0) red[tid >> 5] = mx;
    __syncthreads();
    if (tid == 0) {
        float m = red[0];
        for (int w = 1; w < 8; w++) m = fmaxf(m, red[w]);
        red[8] = m;
    }
    __syncthreads();
    mx = red[8];

    float sum = 0.f;
#pragma unroll
    for (int i = 0; i < 4; i++) { v[i] = __expf(v[i] - mx); sum += v[i]; }
    for (int o = 16; o; o >>= 1) sum += __shfl_xor_sync(0xffffffffu, sum, o);
    __syncthreads();
    if ((tid & 31) == 0) red[tid >> 5] = sum;
    __syncthreads();
    if (tid == 0) {
        float s = 0.f;
        for (int w = 0; w < 8; w++) s += red[w];
        red[8] = 1.0f / s;
    }
    __syncthreads();
    float inv = red[8];
#pragma unroll
    for (int i = 0; i < 4; i++) sc[base + tid + i * 256] = v[i] * inv;
}

// ---------------------------------------------------------------------------
// AV: O[b,q,h,:] = sum_k P[bh,q,k] * V[b,k,h,:]
// grid = (1, SEQ/64, B*NH), 256 threads; 64 q x 64 d tile, K loop over 1024.
// ---------------------------------------------------------------------------
__global__ __launch_bounds__(256)
void attn_av_kernel(const float* __restrict__ P, const float* __restrict__ V,
                    float* __restrict__ O)
{
    __shared__ float Pst[64][65];                 // [k][q] transposed
    __shared__ __align__(16) float Vs[64][68];    // [k][d]

    int bh = blockIdx.z;
    int b  = bh >> 4, h = bh & 15;
    int q0 = blockIdx.y << 6;
    int tid = threadIdx.x, tx = tid & 15, ty = tid >> 4;

    const float* Pb = P + (size_t)bh * SEQ * SEQ + (size_t)q0 * SEQ;
    const float* Vb = V + ((size_t)b * SEQ * NH + h) * HDIM;

    float acc[4][4] = {};
    for (int c0 = 0; c0 < SEQ; c0 += 64) {
#pragma unroll
        for (int it = 0; it < 16; it++) {
            int idx = tid + it * 256;
            int qq = idx >> 6, k = idx & 63;
            Pst[k][qq] = Pb[(size_t)qq * SEQ + c0 + k];
        }
#pragma unroll
        for (int it = 0; it < 4; it++) {
            int idx = tid + it * 256;
            int r = idx >> 4, c = (idx & 15) << 2;
            *(float4*)&Vs[r][c] = *(const float4*)(Vb + (size_t)(c0 + r) * DIM + c);
        }
        __syncthreads();
#pragma unroll 8
        for (int k = 0; k < 64; k++) {
            float4 bv = *(const float4*)&Vs[k][tx * 4];
            float a[4];
#pragma unroll
            for (int i = 0; i < 4; i++) a[i] = Pst[k][ty * 4 + i];
#pragma unroll
            for (int i = 0; i < 4; i++) {
                acc[i][0] = fmaf(a[i], bv.x, acc[i][0]);
                acc[i][1] = fmaf(a[i], bv.y, acc[i][1]);
                acc[i][2] = fmaf(a[i], bv.z, acc[i][2]);
                acc[i][3] = fmaf(a[i], bv.w, acc[i][3]);
            }
        }
        __syncthreads();
    }

    float* Ob = O + ((size_t)(b * SEQ + q0) * NH + h) * HDIM;
#pragma unroll
    for (int i = 0; i < 4; i++) {
        float4 r = make_float4(acc[i][0], acc[i][1], acc[i][2], acc[i][3]);
        *(float4*)(Ob + (size_t)(ty * 4 + i) * DIM + tx * 4) = r;
    }
}

// ---------------------------------------------------------------------------
// x = LayerNorm(x + a) * g + b     (in place on x). grid = MROWS, 256 thr.
// ---------------------------------------------------------------------------
__global__ __launch_bounds__(256)
void add_ln_kernel(float* __restrict__ x, const float* __restrict__ a,
                   const float* __restrict__ g, const float* __restrict__ b)
{
    __shared__ float red[9];
    size_t base = (size_t)blockIdx.x * DIM;
    int tid = threadIdx.x;

    float v[4];
    float s = 0.f;
#pragma unroll
    for (int i = 0; i < 4; i++) {
        int c = tid + i * 256;
        v[i] = x[base + c] + a[base + c];
        s += v[i];
    }
    for (int o = 16; o; o >>= 1) s += __shfl_xor_sync(0xffffffffu, s, o);
    if ((tid & 31) == 0) red[tid >> 5] = s;
    __syncthreads();
    if (tid == 0) {
        float t = 0.f;
        for (int w = 0; w < 8; w++) t += red[w];
        red[8] = t * (1.0f / DIM);
    }
    __syncthreads();
    float mean = red[8];

    float vs = 0.f;
#pragma unroll
    for (int i = 0; i < 4; i++) { float d = v[i] - mean; vs += d * d; }
    for (int o = 16; o; o >>= 1) vs += __shfl_xor_sync(0xffffffffu, vs, o);
    __syncthreads();
    if ((tid & 31) == 0) red[tid >> 5] = vs;
    __syncthreads();
    if (tid == 0) {
        float t = 0.f;
        for (int w = 0; w < 8; w++) t += red[w];
        red[8] = t * (1.0f / DIM);
    }
    __syncthreads();
    float inv = rsqrtf(red[8] + 1e-5f);

#pragma unroll
    for (int i = 0; i < 4; i++) {
        int c = tid + i * 256;
        x[base + c] = (v[i] - mean) * inv * g[c] + b[c];
    }
}

// ---------------------------------------------------------------------------
// Host-side orchestration
// ---------------------------------------------------------------------------
static inline void gemm(const float* A, const float* B, const float* bias,
                        float* C, int M, int N, int K, int relu)
{
    dim3 grid(N / 128, M / 128);
    sgemm_kernel<<<grid, 256>>>(A, B, bias, C, M, N, K, relu);
}

// Full attention sublayer: output (pre-LN) into t.  q/k/v/sc are scratch.
static void attention(const float* Xq, const float* Xkv,
                      const float* W, const float* Bb,
                      const int* tok, int causal,
                      float* q, float* k, float* v, float* t, float* sc)
{
    const size_t DD = (size_t)DIM * DIM;
    gemm(Xq,  W,          Bb,           q, MROWS, DIM, DIM, 0);
    gemm(Xkv, W + DD,     Bb + DIM,     k, MROWS, DIM, DIM, 0);
    gemm(Xkv, W + 2 * DD, Bb + 2 * DIM, v, MROWS, DIM, DIM, 0);
    attn_scores_kernel<<<dim3(SEQ / 64, SEQ / 64, BATCH * NH), 256>>>(q, k, tok, sc, causal);
    softmax_kernel<<<BATCH * NH * SEQ, 256>>>(sc);
    attn_av_kernel<<<dim3(1, SEQ / 64, BATCH * NH), 256>>>(sc, v, q);  // q reused as output
    gemm(q, W + 3 * DD, Bb + 3 * DIM, t, MROWS, DIM, DIM, 0);
}

extern "C" void kernel_launch(void* const* d_in, const int* in_sizes, int n_in,
                              void* d_out, int out_size)
{
    (void)in_sizes; (void)n_in; (void)out_size;

    const int*   src        = (const int*)  d_in[0];
    const int*   trg        = (const int*)  d_in[1];
    const float* src_emb    = (const float*)d_in[2];
    const float* trg_emb    = (const float*)d_in[3];
    const float* enc_attn_w = (const float*)d_in[4];
    const float* enc_attn_b = (const float*)d_in[5];
    const float* enc_ff1_w  = (const float*)d_in[6];
    const float* enc_ff1_b  = (const float*)d_in[7];
    const float* enc_ff2_w  = (const float*)d_in[8];
    const float* enc_ff2_b  = (const float*)d_in[9];
    const float* enc_ln_g   = (const float*)d_in[10];
    const float* enc_ln_b   = (const float*)d_in[11];
    const float* dec_self_w = (const float*)d_in[12];
    const float* dec_self_b = (const float*)d_in[13];
    const float* dec_cross_w= (const float*)d_in[14];
    const float* dec_cross_b= (const float*)d_in[15];
    const float* dec_ff1_w  = (const float*)d_in[16];
    const float* dec_ff1_b  = (const float*)d_in[17];
    const float* dec_ff2_w  = (const float*)d_in[18];
    const float* dec_ff2_b  = (const float*)d_in[19];
    const float* dec_ln_g   = (const float*)d_in[20];
    const float* dec_ln_b   = (const float*)d_in[21];
    const float* out_w      = (const float*)d_in[22];
    const float* out_b      = (const float*)d_in[23];
    float* out = (float*)d_out;

    float *x, *y, *q, *k, *v, *t, *ff, *sc;
    cudaGetSymbolAddress((void**)&x,  g_x);
    cudaGetSymbolAddress((void**)&y,  g_y);
    cudaGetSymbolAddress((void**)&q,  g_q);
    cudaGetSymbolAddress((void**)&k,  g_k);
    cudaGetSymbolAddress((void**)&v,  g_v);
    cudaGetSymbolAddress((void**)&t,  g_t);
    cudaGetSymbolAddress((void**)&ff, g_ff);
    cudaGetSymbolAddress((void**)&sc, g_sc);

    const size_t DD = (size_t)DIM * DIM;

    // -------------------- encoder --------------------
    embed_kernel<<<MROWS, 256>>>(src, src_emb, x);
    for (int l = 0; l < NL; l++) {
        attention(x, x, enc_attn_w + (size_t)l * 4 * DD, enc_attn_b + (size_t)l * 4 * DIM,
                  src, /*causal=*/0, q, k, v, t, sc);
        add_ln_kernel<<<MROWS, 256>>>(x, t,
            enc_ln_g + (size_t)(l * 2 + 0) * DIM, enc_ln_b + (size_t)(l * 2 + 0) * DIM);

        gemm(x,  enc_ff1_w + (size_t)l * DIM * FFD, enc_ff1_b + (size_t)l * FFD, ff,
             MROWS, FFD, DIM, 1);
        gemm(ff, enc_ff2_w + (size_t)l * FFD * DIM, enc_ff2_b + (size_t)l * DIM, t,
             MROWS, DIM, FFD, 0);
        add_ln_kernel<<<MROWS, 256>>>(x, t,
            enc_ln_g + (size_t)(l * 2 + 1) * DIM, enc_ln_b + (size_t)(l * 2 + 1) * DIM);
    }

    // -------------------- decoder --------------------
    embed_kernel<<<MROWS, 256>>>(trg, trg_emb, y);
    for (int l = 0; l < NL; l++) {
        // masked self-attention
        attention(y, y, dec_self_w + (size_t)l * 4 * DD, dec_self_b + (size_t)l * 4 * DIM,
                  trg, /*causal=*/1, q, k, v, t, sc);
        add_ln_kernel<<<MROWS, 256>>>(y, t,
            dec_ln_g + (size_t)(l * 3 + 0) * DIM, dec_ln_b + (size_t)(l * 3 + 0) * DIM);

        // cross-attention (K/V from encoder output x)
        attention(y, x, dec_cross_w + (size_t)l * 4 * DD, dec_cross_b + (size_t)l * 4 * DIM,
                  src, /*causal=*/0, q, k, v, t, sc);
        add_ln_kernel<<<MROWS, 256>>>(y, t,
            dec_ln_g + (size_t)(l * 3 + 1) * DIM, dec_ln_b + (size_t)(l * 3 + 1) * DIM);

        // feed-forward
        gemm(y,  dec_ff1_w + (size_t)l * DIM * FFD, dec_ff1_b + (size_t)l * FFD, ff,
             MROWS, FFD, DIM, 1);
        gemm(ff, dec_ff2_w + (size_t)l * FFD * DIM, dec_ff2_b + (size_t)l * DIM, t,
             MROWS, DIM, FFD, 0);
        add_ln_kernel<<<MROWS, 256>>>(y, t,
            dec_ln_g + (size_t)(l * 3 + 2) * DIM, dec_ln_b + (size_t)(l * 3 + 2) * DIM);
    }

    // -------------------- output projection --------------------
    gemm(y, out_w, out_b, out, MROWS, VOCAB, DIM, 0);
}

// round 8
// speedup vs baseline: 1.0004x; 1.0004x over previous
#include <cuda_runtime.h>

// ---------------------------------------------------------------------------
// Problem constants
// ---------------------------------------------------------------------------
#define DIM   1024         // model dim D
#define SEQ   1024         // SS == ST
#define BATCH 4
#define NH    16
#define HDIM  64
#define FFD   4096
#define NL    6
#define MROWS (BATCH * SEQ)   // 4096
#define VOCAB 32000

// ---------------------------------------------------------------------------
// Scratch (static device globals -- no allocation allowed)
// ---------------------------------------------------------------------------
__device__ float g_x [MROWS * DIM];          // encoder activations
__device__ float g_y [MROWS * DIM];          // decoder activations
__device__ float g_q [MROWS * DIM];          // Q / attention-out reuse
__device__ float g_k [MROWS * DIM];
__device__ float g_v [MROWS * DIM];
__device__ float g_t [MROWS * DIM];          // sublayer output (pre-LN)
__device__ float g_ff[MROWS * FFD];          // FF intermediate
__device__ float g_sc[(size_t)BATCH * NH * SEQ * SEQ];   // attention scores (268 MB)

// ---------------------------------------------------------------------------
// Embedding + sinusoidal positional encoding
// grid = MROWS blocks, 256 threads
// ---------------------------------------------------------------------------
__global__ __launch_bounds__(256)
void embed_kernel(const int* __restrict__ tok, const float* __restrict__ emb,
                  float* __restrict__ out)
{
    int bs = blockIdx.x;
    int s  = bs & (SEQ - 1);
    int t  = tok[bs];
    const float* e = emb + (size_t)t * DIM;
    float* o = out + (size_t)bs * DIM;
    const float c = (float)(-9.210340371976184 / 1024.0);   // -ln(10000)/D
#pragma unroll
    for (int i = 0; i < 4; i++) {
        int d  = threadIdx.x + i * 256;
        int i2 = d & ~1;
        float div = expf((float)i2 * c);
        float ang = (float)s * div;
        float pe  = (d & 1) ? cosf(ang) : sinf(ang);
        o[d] = e[d] + pe;
    }
}

// ---------------------------------------------------------------------------
// SGEMM: C[M,N] = A[M,K] @ B[K,N] + bias[N]   (optional ReLU)
// Requires M%128==0, N%128==0, K%8==0 (true for all call sites).
// 128x128 block tile, BK=8, 256 threads, 8x8 per thread (2x2 split warp tile).
// ---------------------------------------------------------------------------
__global__ __launch_bounds__(256, 2)
void sgemm_kernel(const float* __restrict__ A, const float* __restrict__ B,
                  const float* __restrict__ bias, float* __restrict__ C,
                  int M, int N, int K, int relu)
{
    __shared__ __align__(16) float As[8][128];
    __shared__ __align__(16) float Bs[8][128];

    const int tid  = threadIdx.x;
    const int brow = blockIdx.y << 7;
    const int bcol = blockIdx.x << 7;
    const int tx   = tid & 15;
    const int ty   = tid >> 4;

    const int a_row = tid >> 1;
    const int a_col = (tid & 1) << 2;
    const int b_row = tid >> 5;
    const int b_col = (tid & 31) << 2;

    const float* Ap = A + (size_t)(brow + a_row) * K + a_col;
    const float* Bp = B + (size_t)b_row * N + bcol + b_col;

    float acc[8][8];
#pragma unroll
    for (int i = 0; i < 8; i++)
#pragma unroll
        for (int j = 0; j < 8; j++) acc[i][j] = 0.f;

    for (int k0 = 0; k0 < K; k0 += 8) {
        float4 av = *(const float4*)Ap;
        float4 bv = *(const float4*)Bp;
        As[a_col + 0][a_row] = av.x;
        As[a_col + 1][a_row] = av.y;
        As[a_col + 2][a_row] = av.z;
        As[a_col + 3][a_row] = av.w;
        *(float4*)&Bs[b_row][b_col] = bv;
        __syncthreads();
#pragma unroll
        for (int kk = 0; kk < 8; kk++) {
            float4 a0 = *(const float4*)&As[kk][ty * 4];
            float4 a1 = *(const float4*)&As[kk][ty * 4 + 64];
            float4 b0 = *(const float4*)&Bs[kk][tx * 4];
            float4 b1 = *(const float4*)&Bs[kk][tx * 4 + 64];
            float ar[8] = {a0.x, a0.y, a0.z, a0.w, a1.x, a1.y, a1.z, a1.w};
            float br[8] = {b0.x, b0.y, b0.z, b0.w, b1.x, b1.y, b1.z, b1.w};
#pragma unroll
            for (int i = 0; i < 8; i++)
#pragma unroll
                for (int j = 0; j < 8; j++)
                    acc[i][j] = fmaf(ar[i], br[j], acc[i][j]);
        }
        __syncthreads();
        Ap += 8;
        Bp += (size_t)8 * N;
    }

#pragma unroll
    for (int i = 0; i < 8; i++) {
        int row = brow + ((i < 4) ? (ty * 4 + i) : (64 + ty * 4 + (i - 4)));
#pragma unroll
        for (int jh = 0; jh < 2; jh++) {
            int col = bcol + jh * 64 + tx * 4;
            float4 bb = *(const float4*)&bias[col];
            float4 r;
            r.x = acc[i][jh * 4 + 0] + bb.x;
            r.y = acc[i][jh * 4 + 1] + bb.y;
            r.z = acc[i][jh * 4 + 2] + bb.z;
            r.w = acc[i][jh * 4 + 3] + bb.w;
            if (relu) {
                r.x = fmaxf(r.x, 0.f); r.y = fmaxf(r.y, 0.f);
                r.z = fmaxf(r.z, 0.f); r.w = fmaxf(r.w, 0.f);
            }
            *(float4*)&C[(size_t)row * N + col] = r;
        }
    }
}

// ---------------------------------------------------------------------------
// Attention scores: sc[bh, q, k] = dot(Q[b,q,h,:], K[b,k,h,:]) / 8, masked.
// causal==0: mask k where tok[b,k]==0 (src pad mask)
// causal==1: mask unless tok[b,q]!=0 && k<=q      (trg pad & causal)
// grid = (SEQ/64, SEQ/64, B*NH), 256 threads; 64x64 tile, 4x4 per thread.
// ---------------------------------------------------------------------------
__global__ __launch_bounds__(256)
void attn_scores_kernel(const float* __restrict__ Q, const float* __restrict__ Km,
                        const int* __restrict__ tok, float* __restrict__ sc,
                        int causal)
{
    __shared__ __align__(16) float Qs[64][68];
    __shared__ __align__(16) float Ks[64][68];

    int bh = blockIdx.z;
    int b  = bh >> 4, h = bh & 15;
    int q0 = blockIdx.y << 6, k0 = blockIdx.x << 6;
    int tid = threadIdx.x;

    const float* Qb = Q  + ((size_t)(b * SEQ + q0) * NH + h) * HDIM;
    const float* Kb = Km + ((size_t)(b * SEQ + k0) * NH + h) * HDIM;

#pragma unroll
    for (int it = 0; it < 4; it++) {
        int idx = tid + it * 256;
        int r = idx >> 4, c = (idx & 15) << 2;
        *(float4*)&Qs[r][c] = *(const float4*)(Qb + (size_t)r * DIM + c);
        *(float4*)&Ks[r][c] = *(const float4*)(Kb + (size_t)r * DIM + c);
    }
    __syncthreads();

    int tx = tid & 15, ty = tid >> 4;
    float acc[4][4] = {};
#pragma unroll 4
    for (int d0 = 0; d0 < 64; d0 += 4) {
        float4 qv[4], kv[4];
#pragma unroll
        for (int i = 0; i < 4; i++) qv[i] = *(const float4*)&Qs[ty * 4 + i][d0];
#pragma unroll
        for (int j = 0; j < 4; j++) kv[j] = *(const float4*)&Ks[tx + 16 * j][d0];
#pragma unroll
        for (int i = 0; i < 4; i++)
#pragma unroll
            for (int j = 0; j < 4; j++)
                acc[i][j] += qv[i].x * kv[j].x + qv[i].y * kv[j].y
                           + qv[i].z * kv[j].z + qv[i].w * kv[j].w;
    }

    const float scale = 0.125f;   // 1/sqrt(64)
    size_t sbase = (size_t)bh * SEQ * SEQ;
    int qok[4];
#pragma unroll
    for (int i = 0; i < 4; i++)
        qok[i] = causal ? (tok[b * SEQ + q0 + ty * 4 + i] != 0) : 1;
#pragma unroll
    for (int j = 0; j < 4; j++) {
        int k = k0 + tx + 16 * j;
        int kok = causal ? 1 : (tok[b * SEQ + k] != 0);
#pragma unroll
        for (int i = 0; i < 4; i++) {
            int q = q0 + ty * 4 + i;
            int ok = causal ? (qok[i] && (k <= q)) : kok;
            sc[sbase + (size_t)q * SEQ + k] = ok ? acc[i][j] * scale : -1e9f;
        }
    }
}

// ---------------------------------------------------------------------------
// Row softmax (in place). grid = B*NH*SEQ blocks, 256 threads, row len 1024.
// ---------------------------------------------------------------------------
__global__ __launch_bounds__(256)
void softmax_kernel(float* __restrict__ sc)
{
    __shared__ float red[9];
    size_t base = (size_t)blockIdx.x * SEQ;
    int tid = threadIdx.x;

    float v[4];
    float mx = -3.4e38f;
#pragma unroll
    for (int i = 0; i < 4; i++) {
        v[i] = sc[base + tid + i * 256];
        mx = fmaxf(mx, v[i]);
    }
    for (int o = 16; o; o >>= 1) mx = fmaxf(mx, __shfl_xor_sync(0xffffffffu, mx, o));
    if ((tid & 31) == 0) red[tid >> 5] = mx;
    __syncthreads();
    if (tid == 0) {
        float m = red[0];
        for (int w = 1; w < 8; w++) m = fmaxf(m, red[w]);
        red[8] = m;
    }
    __syncthreads();
    mx = red[8];

    float sum = 0.f;
#pragma unroll
    for (int i = 0; i < 4; i++) { v[i] = __expf(v[i] - mx); sum += v[i]; }
    for (int o = 16; o; o >>= 1) sum += __shfl_xor_sync(0xffffffffu, sum, o);
    __syncthreads();
    if ((tid & 31) == 0) red[tid >> 5] = sum;
    __syncthreads();
    if (tid == 0) {
        float s = 0.f;
        for (int w = 0; w < 8; w++) s += red[w];
        red[8] = 1.0f / s;
    }
    __syncthreads();
    float inv = red[8];
#pragma unroll
    for (int i = 0; i < 4; i++) sc[base + tid + i * 256] = v[i] * inv;
}

// ---------------------------------------------------------------------------
// AV: O[b,q,h,:] = sum_k P[bh,q,k] * V[b,k,h,:]
// grid = (1, SEQ/64, B*NH), 256 threads; 64 q x 64 d tile, K loop over 1024.
// ---------------------------------------------------------------------------
__global__ __launch_bounds__(256)
void attn_av_kernel(const float* __restrict__ P, const float* __restrict__ V,
                    float* __restrict__ O)
{
    __shared__ float Pst[64][65];                 // [k][q] transposed
    __shared__ __align__(16) float Vs[64][68];    // [k][d]

    int bh = blockIdx.z;
    int b  = bh >> 4, h = bh & 15;
    int q0 = blockIdx.y << 6;
    int tid = threadIdx.x, tx = tid & 15, ty = tid >> 4;

    const float* Pb = P + (size_t)bh * SEQ * SEQ + (size_t)q0 * SEQ;
    const float* Vb = V + ((size_t)b * SEQ * NH + h) * HDIM;

    float acc[4][4] = {};
    for (int c0 = 0; c0 < SEQ; c0 += 64) {
#pragma unroll
        for (int it = 0; it < 16; it++) {
            int idx = tid + it * 256;
            int qq = idx >> 6, k = idx & 63;
            Pst[k][qq] = Pb[(size_t)qq * SEQ + c0 + k];
        }
#pragma unroll
        for (int it = 0; it < 4; it++) {
            int idx = tid + it * 256;
            int r = idx >> 4, c = (idx & 15) << 2;
            *(float4*)&Vs[r][c] = *(const float4*)(Vb + (size_t)(c0 + r) * DIM + c);
        }
        __syncthreads();
#pragma unroll 8
        for (int k = 0; k < 64; k++) {
            float4 bv = *(const float4*)&Vs[k][tx * 4];
            float a[4];
#pragma unroll
            for (int i = 0; i < 4; i++) a[i] = Pst[k][ty * 4 + i];
#pragma unroll
            for (int i = 0; i < 4; i++) {
                acc[i][0] = fmaf(a[i], bv.x, acc[i][0]);
                acc[i][1] = fmaf(a[i], bv.y, acc[i][1]);
                acc[i][2] = fmaf(a[i], bv.z, acc[i][2]);
                acc[i][3] = fmaf(a[i], bv.w, acc[i][3]);
            }
        }
        __syncthreads();
    }

    float* Ob = O + ((size_t)(b * SEQ + q0) * NH + h) * HDIM;
#pragma unroll
    for (int i = 0; i < 4; i++) {
        float4 r = make_float4(acc[i][0], acc[i][1], acc[i][2], acc[i][3]);
        *(float4*)(Ob + (size_t)(ty * 4 + i) * DIM + tx * 4) = r;
    }
}

// ---------------------------------------------------------------------------
// x = LayerNorm(x + a) * g + b     (in place on x). grid = MROWS, 256 thr.
// ---------------------------------------------------------------------------
__global__ __launch_bounds__(256)
void add_ln_kernel(float* __restrict__ x, const float* __restrict__ a,
                   const float* __restrict__ g, const float* __restrict__ b)
{
    __shared__ float red[9];
    size_t base = (size_t)blockIdx.x * DIM;
    int tid = threadIdx.x;

    float v[4];
    float s = 0.f;
#pragma unroll
    for (int i = 0; i < 4; i++) {
        int c = tid + i * 256;
        v[i] = x[base + c] + a[base + c];
        s += v[i];
    }
    for (int o = 16; o; o >>= 1) s += __shfl_xor_sync(0xffffffffu, s, o);
    if ((tid & 31) == 0) red[tid >> 5] = s;
    __syncthreads();
    if (tid == 0) {
        float t = 0.f;
        for (int w = 0; w < 8; w++) t += red[w];
        red[8] = t * (1.0f / DIM);
    }
    __syncthreads();
    float mean = red[8];

    float vs = 0.f;
#pragma unroll
    for (int i = 0; i < 4; i++) { float d = v[i] - mean; vs += d * d; }
    for (int o = 16; o; o >>= 1) vs += __shfl_xor_sync(0xffffffffu, vs, o);
    __syncthreads();
    if ((tid & 31) == 0) red[tid >> 5] = vs;
    __syncthreads();
    if (tid == 0) {
        float t = 0.f;
        for (int w = 0; w < 8; w++) t += red[w];
        red[8] = t * (1.0f / DIM);
    }
    __syncthreads();
    float inv = rsqrtf(red[8] + 1e-5f);

#pragma unroll
    for (int i = 0; i < 4; i++) {
        int c = tid + i * 256;
        x[base + c] = (v[i] - mean) * inv * g[c] + b[c];
    }
}

// ---------------------------------------------------------------------------
// Host-side orchestration
// ---------------------------------------------------------------------------
static inline void gemm(const float* A, const float* B, const float* bias,
                        float* C, int M, int N, int K, int relu)
{
    dim3 grid(N / 128, M / 128);
    sgemm_kernel<<<grid, 256>>>(A, B, bias, C, M, N, K, relu);
}

// Full attention sublayer: output (pre-LN) into t.  q/k/v/sc are scratch.
static void attention(const float* Xq, const float* Xkv,
                      const float* W, const float* Bb,
                      const int* tok, int causal,
                      float* q, float* k, float* v, float* t, float* sc)
{
    const size_t DD = (size_t)DIM * DIM;
    gemm(Xq,  W,          Bb,           q, MROWS, DIM, DIM, 0);
    gemm(Xkv, W + DD,     Bb + DIM,     k, MROWS, DIM, DIM, 0);
    gemm(Xkv, W + 2 * DD, Bb + 2 * DIM, v, MROWS, DIM, DIM, 0);
    attn_scores_kernel<<<dim3(SEQ / 64, SEQ / 64, BATCH * NH), 256>>>(q, k, tok, sc, causal);
    softmax_kernel<<<BATCH * NH * SEQ, 256>>>(sc);
    attn_av_kernel<<<dim3(1, SEQ / 64, BATCH * NH), 256>>>(sc, v, q);  // q reused as output
    gemm(q, W + 3 * DD, Bb + 3 * DIM, t, MROWS, DIM, DIM, 0);
}

extern "C" void kernel_launch(void* const* d_in, const int* in_sizes, int n_in,
                              void* d_out, int out_size)
{
    (void)in_sizes; (void)n_in; (void)out_size;

    const int*   src        = (const int*)  d_in[0];
    const int*   trg        = (const int*)  d_in[1];
    const float* src_emb    = (const float*)d_in[2];
    const float* trg_emb    = (const float*)d_in[3];
    const float* enc_attn_w = (const float*)d_in[4];
    const float* enc_attn_b = (const float*)d_in[5];
    const float* enc_ff1_w  = (const float*)d_in[6];
    const float* enc_ff1_b  = (const float*)d_in[7];
    const float* enc_ff2_w  = (const float*)d_in[8];
    const float* enc_ff2_b  = (const float*)d_in[9];
    const float* enc_ln_g   = (const float*)d_in[10];
    const float* enc_ln_b   = (const float*)d_in[11];
    const float* dec_self_w = (const float*)d_in[12];
    const float* dec_self_b = (const float*)d_in[13];
    const float* dec_cross_w= (const float*)d_in[14];
    const float* dec_cross_b= (const float*)d_in[15];
    const float* dec_ff1_w  = (const float*)d_in[16];
    const float* dec_ff1_b  = (const float*)d_in[17];
    const float* dec_ff2_w  = (const float*)d_in[18];
    const float* dec_ff2_b  = (const float*)d_in[19];
    const float* dec_ln_g   = (const float*)d_in[20];
    const float* dec_ln_b   = (const float*)d_in[21];
    const float* out_w      = (const float*)d_in[22];
    const float* out_b      = (const float*)d_in[23];
    float* out = (float*)d_out;

    float *x, *y, *q, *k, *v, *t, *ff, *sc;
    cudaGetSymbolAddress((void**)&x,  g_x);
    cudaGetSymbolAddress((void**)&y,  g_y);
    cudaGetSymbolAddress((void**)&q,  g_q);
    cudaGetSymbolAddress((void**)&k,  g_k);
    cudaGetSymbolAddress((void**)&v,  g_v);
    cudaGetSymbolAddress((void**)&t,  g_t);
    cudaGetSymbolAddress((void**)&ff, g_ff);
    cudaGetSymbolAddress((void**)&sc, g_sc);

    const size_t DD = (size_t)DIM * DIM;

    // -------------------- encoder --------------------
    embed_kernel<<<MROWS, 256>>>(src, src_emb, x);
    for (int l = 0; l < NL; l++) {
        attention(x, x, enc_attn_w + (size_t)l * 4 * DD, enc_attn_b + (size_t)l * 4 * DIM,
                  src, /*causal=*/0, q, k, v, t, sc);
        add_ln_kernel<<<MROWS, 256>>>(x, t,
            enc_ln_g + (size_t)(l * 2 + 0) * DIM, enc_ln_b + (size_t)(l * 2 + 0) * DIM);

        gemm(x,  enc_ff1_w + (size_t)l * DIM * FFD, enc_ff1_b + (size_t)l * FFD, ff,
             MROWS, FFD, DIM, 1);
        gemm(ff, enc_ff2_w + (size_t)l * FFD * DIM, enc_ff2_b + (size_t)l * DIM, t,
             MROWS, DIM, FFD, 0);
        add_ln_kernel<<<MROWS, 256>>>(x, t,
            enc_ln_g + (size_t)(l * 2 + 1) * DIM, enc_ln_b + (size_t)(l * 2 + 1) * DIM);
    }

    // -------------------- decoder --------------------
    embed_kernel<<<MROWS, 256>>>(trg, trg_emb, y);
    for (int l = 0; l < NL; l++) {
        // masked self-attention
        attention(y, y, dec_self_w + (size_t)l * 4 * DD, dec_self_b + (size_t)l * 4 * DIM,
                  trg, /*causal=*/1, q, k, v, t, sc);
        add_ln_kernel<<<MROWS, 256>>>(y, t,
            dec_ln_g + (size_t)(l * 3 + 0) * DIM, dec_ln_b + (size_t)(l * 3 + 0) * DIM);

        // cross-attention (K/V from encoder output x)
        attention(y, x, dec_cross_w + (size_t)l * 4 * DD, dec_cross_b + (size_t)l * 4 * DIM,
                  src, /*causal=*/0, q, k, v, t, sc);
        add_ln_kernel<<<MROWS, 256>>>(y, t,
            dec_ln_g + (size_t)(l * 3 + 1) * DIM, dec_ln_b + (size_t)(l * 3 + 1) * DIM);

        // feed-forward
        gemm(y,  dec_ff1_w + (size_t)l * DIM * FFD, dec_ff1_b + (size_t)l * FFD, ff,
             MROWS, FFD, DIM, 1);
        gemm(ff, dec_ff2_w + (size_t)l * FFD * DIM, dec_ff2_b + (size_t)l * DIM, t,
             MROWS, DIM, FFD, 0);
        add_ln_kernel<<<MROWS, 256>>>(y, t,
            dec_ln_g + (size_t)(l * 3 + 2) * DIM, dec_ln_b + (size_t)(l * 3 + 2) * DIM);
    }

    // -------------------- output projection --------------------
    gemm(y, out_w, out_b, out, MROWS, VOCAB, DIM, 0);
}

// round 9
// speedup vs baseline: 1.0829x; 1.0824x over previous
#include <cuda_runtime.h>

// ---------------------------------------------------------------------------
// Problem constants
// ---------------------------------------------------------------------------
#define DIM   1024         // model dim D
#define SEQ   1024         // SS == ST
#define BATCH 4
#define NH    16
#define HDIM  64
#define FFD   4096
#define NL    6
#define MROWS (BATCH * SEQ)   // 4096
#define VOCAB 32000

// ---------------------------------------------------------------------------
// Scratch (static device globals -- no allocation allowed)
// ---------------------------------------------------------------------------
__device__ float g_x [MROWS * DIM];          // encoder activations
__device__ float g_y [MROWS * DIM];          // decoder activations
__device__ float g_q [MROWS * DIM];          // Q / attention-out reuse
__device__ float g_k [MROWS * DIM];
__device__ float g_v [MROWS * DIM];
__device__ float g_t [MROWS * DIM];          // sublayer output (pre-LN)
__device__ float g_ff[MROWS * FFD];          // FF intermediate
__device__ float g_sc[(size_t)BATCH * NH * SEQ * SEQ];   // attention scores (268 MB)

// ---------------------------------------------------------------------------
// Embedding + sinusoidal positional encoding
// ---------------------------------------------------------------------------
__global__ __launch_bounds__(256)
void embed_kernel(const int* __restrict__ tok, const float* __restrict__ emb,
                  float* __restrict__ out)
{
    int bs = blockIdx.x;
    int s  = bs & (SEQ - 1);
    int t  = tok[bs];
    const float* e = emb + (size_t)t * DIM;
    float* o = out + (size_t)bs * DIM;
    const float c = (float)(-9.210340371976184 / 1024.0);   // -ln(10000)/D
#pragma unroll
    for (int i = 0; i < 4; i++) {
        int d  = threadIdx.x + i * 256;
        int i2 = d & ~1;
        float div = expf((float)i2 * c);
        float ang = (float)s * div;
        float pe  = (d & 1) ? cosf(ang) : sinf(ang);
        o[d] = e[d] + pe;
    }
}

// ---------------------------------------------------------------------------
// SGEMM: C[M,N] = A[M,K] @ B[K,N] + bias[N]   (optional ReLU)
// 128x128 block tile, BK=8, 256 threads, 8x8 per thread (2x2 split warp tile).
// Double-buffered shared memory: one __syncthreads per K-tile; next tile's
// global loads issue before the compute loop so LDG latency hides under FMAs.
// ---------------------------------------------------------------------------
__global__ __launch_bounds__(256, 2)
void sgemm_kernel(const float* __restrict__ A, const float* __restrict__ B,
                  const float* __restrict__ bias, float* __restrict__ C,
                  int M, int N, int K, int relu)
{
    __shared__ __align__(16) float As[2][8][128];
    __shared__ __align__(16) float Bs[2][8][128];

    const int tid  = threadIdx.x;
    const int brow = blockIdx.y << 7;
    const int bcol = blockIdx.x << 7;
    const int tx   = tid & 15;
    const int ty   = tid >> 4;

    const int a_row = tid >> 1;
    const int a_col = (tid & 1) << 2;
    const int b_row = tid >> 5;
    const int b_col = (tid & 31) << 2;

    const float* Ap = A + (size_t)(brow + a_row) * K + a_col;
    const float* Bp = B + (size_t)b_row * N + bcol + b_col;

    // ---- preload K-tile 0 into buffer 0 ----
    float4 av = *(const float4*)Ap;
    float4 bv = *(const float4*)Bp;
    As[0][a_col + 0][a_row] = av.x;
    As[0][a_col + 1][a_row] = av.y;
    As[0][a_col + 2][a_row] = av.z;
    As[0][a_col + 3][a_row] = av.w;
    *(float4*)&Bs[0][b_row][b_col] = bv;
    __syncthreads();

    float acc[8][8];
#pragma unroll
    for (int i = 0; i < 8; i++)
#pragma unroll
        for (int j = 0; j < 8; j++) acc[i][j] = 0.f;

    int buf = 0;
    for (int k0 = 8; k0 <= K; k0 += 8) {
        // issue next tile's global loads first (latency hides under compute)
        if (k0 < K) {
            av = *(const float4*)(Ap + k0);
            bv = *(const float4*)(Bp + (size_t)k0 * N);
        }

        const float (*Asb)[128] = As[buf];
        const float (*Bsb)[128] = Bs[buf];
#pragma unroll
        for (int kk = 0; kk < 8; kk++) {
            float4 a0 = *(const float4*)&Asb[kk][ty * 4];
            float4 a1 = *(const float4*)&Asb[kk][ty * 4 + 64];
            float4 b0 = *(const float4*)&Bsb[kk][tx * 4];
            float4 b1 = *(const float4*)&Bsb[kk][tx * 4 + 64];
            float ar[8] = {a0.x, a0.y, a0.z, a0.w, a1.x, a1.y, a1.z, a1.w};
            float br[8] = {b0.x, b0.y, b0.z, b0.w, b1.x, b1.y, b1.z, b1.w};
#pragma unroll
            for (int i = 0; i < 8; i++)
#pragma unroll
                for (int j = 0; j < 8; j++)
                    acc[i][j] = fmaf(ar[i], br[j], acc[i][j]);
        }

        if (k0 < K) {
            int nb = buf ^ 1;
            As[nb][a_col + 0][a_row] = av.x;
            As[nb][a_col + 1][a_row] = av.y;
            As[nb][a_col + 2][a_row] = av.z;
            As[nb][a_col + 3][a_row] = av.w;
            *(float4*)&Bs[nb][b_row][b_col] = bv;
            __syncthreads();     // writes to nb visible; reads of buf complete
        }
        buf ^= 1;
    }

#pragma unroll
    for (int i = 0; i < 8; i++) {
        int row = brow + ((i < 4) ? (ty * 4 + i) : (64 + ty * 4 + (i - 4)));
#pragma unroll
        for (int jh = 0; jh < 2; jh++) {
            int col = bcol + jh * 64 + tx * 4;
            float4 bb = *(const float4*)&bias[col];
            float4 r;
            r.x = acc[i][jh * 4 + 0] + bb.x;
            r.y = acc[i][jh * 4 + 1] + bb.y;
            r.z = acc[i][jh * 4 + 2] + bb.z;
            r.w = acc[i][jh * 4 + 3] + bb.w;
            if (relu) {
                r.x = fmaxf(r.x, 0.f); r.y = fmaxf(r.y, 0.f);
                r.z = fmaxf(r.z, 0.f); r.w = fmaxf(r.w, 0.f);
            }
            *(float4*)&C[(size_t)row * N + col] = r;
        }
    }
}

// ---------------------------------------------------------------------------
// Attention scores: sc[bh, q, k] = dot(Q[b,q,h,:], K[b,k,h,:]) / 8, masked.
// ---------------------------------------------------------------------------
__global__ __launch_bounds__(256)
void attn_scores_kernel(const float* __restrict__ Q, const float* __restrict__ Km,
                        const int* __restrict__ tok, float* __restrict__ sc,
                        int causal)
{
    __shared__ __align__(16) float Qs[64][68];
    __shared__ __align__(16) float Ks[64][68];

    int bh = blockIdx.z;
    int b  = bh >> 4, h = bh & 15;
    int q0 = blockIdx.y << 6, k0 = blockIdx.x << 6;
    int tid = threadIdx.x;

    const float* Qb = Q  + ((size_t)(b * SEQ + q0) * NH + h) * HDIM;
    const float* Kb = Km + ((size_t)(b * SEQ + k0) * NH + h) * HDIM;

#pragma unroll
    for (int it = 0; it < 4; it++) {
        int idx = tid + it * 256;
        int r = idx >> 4, c = (idx & 15) << 2;
        *(float4*)&Qs[r][c] = *(const float4*)(Qb + (size_t)r * DIM + c);
        *(float4*)&Ks[r][c] = *(const float4*)(Kb + (size_t)r * DIM + c);
    }
    __syncthreads();

    int tx = tid & 15, ty = tid >> 4;
    float acc[4][4] = {};
#pragma unroll 4
    for (int d0 = 0; d0 < 64; d0 += 4) {
        float4 qv[4], kv[4];
#pragma unroll
        for (int i = 0; i < 4; i++) qv[i] = *(const float4*)&Qs[ty * 4 + i][d0];
#pragma unroll
        for (int j = 0; j < 4; j++) kv[j] = *(const float4*)&Ks[tx + 16 * j][d0];
#pragma unroll
        for (int i = 0; i < 4; i++)
#pragma unroll
            for (int j = 0; j < 4; j++)
                acc[i][j] += qv[i].x * kv[j].x + qv[i].y * kv[j].y
                           + qv[i].z * kv[j].z + qv[i].w * kv[j].w;
    }

    const float scale = 0.125f;   // 1/sqrt(64)
    size_t sbase = (size_t)bh * SEQ * SEQ;
    int qok[4];
#pragma unroll
    for (int i = 0; i < 4; i++)
        qok[i] = causal ? (tok[b * SEQ + q0 + ty * 4 + i] != 0) : 1;
#pragma unroll
    for (int j = 0; j < 4; j++) {
        int k = k0 + tx + 16 * j;
        int kok = causal ? 1 : (tok[b * SEQ + k] != 0);
#pragma unroll
        for (int i = 0; i < 4; i++) {
            int q = q0 + ty * 4 + i;
            int ok = causal ? (qok[i] && (k <= q)) : kok;
            sc[sbase + (size_t)q * SEQ + k] = ok ? acc[i][j] * scale : -1e9f;
        }
    }
}

// ---------------------------------------------------------------------------
// Row softmax (in place). grid = B*NH*SEQ blocks, 256 threads, row len 1024.
// ---------------------------------------------------------------------------
__global__ __launch_bounds__(256)
void softmax_kernel(float* __restrict__ sc)
{
    __shared__ float red[9];
    size_t base = (size_t)blockIdx.x * SEQ;
    int tid = threadIdx.x;

    float v[4];
    float mx = -3.4e38f;
#pragma unroll
    for (int i = 0; i < 4; i++) {
        v[i] = sc[base + tid + i * 256];
        mx = fmaxf(mx, v[i]);
    }
    for (int o = 16; o; o >>= 1) mx = fmaxf(mx, __shfl_xor_sync(0xffffffffu, mx, o));
    if ((tid & 31) == 0) red[tid >> 5] = mx;
    __syncthreads();
    if (tid == 0) {
        float m = red[0];
        for (int w = 1; w < 8; w++) m = fmaxf(m, red[w]);
        red[8] = m;
    }
    __syncthreads();
    mx = red[8];

    float sum = 0.f;
#pragma unroll
    for (int i = 0; i < 4; i++) { v[i] = __expf(v[i] - mx); sum += v[i]; }
    for (int o = 16; o; o >>= 1) sum += __shfl_xor_sync(0xffffffffu, sum, o);
    __syncthreads();
    if ((tid & 31) == 0) red[tid >> 5] = sum;
    __syncthreads();
    if (tid == 0) {
        float s = 0.f;
        for (int w = 0; w < 8; w++) s += red[w];
        red[8] = 1.0f / s;
    }
    __syncthreads();
    float inv = red[8];
#pragma unroll
    for (int i = 0; i < 4; i++) sc[base + tid + i * 256] = v[i] * inv;
}

// ---------------------------------------------------------------------------
// AV: O[b,q,h,:] = sum_k P[bh,q,k] * V[b,k,h,:]
// ---------------------------------------------------------------------------
__global__ __launch_bounds__(256)
void attn_av_kernel(const float* __restrict__ P, const float* __restrict__ V,
                    float* __restrict__ O)
{
    __shared__ float Pst[64][65];                 // [k][q] transposed
    __shared__ __align__(16) float Vs[64][68];    // [k][d]

    int bh = blockIdx.z;
    int b  = bh >> 4, h = bh & 15;
    int q0 = blockIdx.y << 6;
    int tid = threadIdx.x, tx = tid & 15, ty = tid >> 4;

    const float* Pb = P + (size_t)bh * SEQ * SEQ + (size_t)q0 * SEQ;
    const float* Vb = V + ((size_t)b * SEQ * NH + h) * HDIM;

    float acc[4][4] = {};
    for (int c0 = 0; c0 < SEQ; c0 += 64) {
#pragma unroll
        for (int it = 0; it < 16; it++) {
            int idx = tid + it * 256;
            int qq = idx >> 6, k = idx & 63;
            Pst[k][qq] = Pb[(size_t)qq * SEQ + c0 + k];
        }
#pragma unroll
        for (int it = 0; it < 4; it++) {
            int idx = tid + it * 256;
            int r = idx >> 4, c = (idx & 15) << 2;
            *(float4*)&Vs[r][c] = *(const float4*)(Vb + (size_t)(c0 + r) * DIM + c);
        }
        __syncthreads();
#pragma unroll 8
        for (int k = 0; k < 64; k++) {
            float4 bv = *(const float4*)&Vs[k][tx * 4];
            float a[4];
#pragma unroll
            for (int i = 0; i < 4; i++) a[i] = Pst[k][ty * 4 + i];
#pragma unroll
            for (int i = 0; i < 4; i++) {
                acc[i][0] = fmaf(a[i], bv.x, acc[i][0]);
                acc[i][1] = fmaf(a[i], bv.y, acc[i][1]);
                acc[i][2] = fmaf(a[i], bv.z, acc[i][2]);
                acc[i][3] = fmaf(a[i], bv.w, acc[i][3]);
            }
        }
        __syncthreads();
    }

    float* Ob = O + ((size_t)(b * SEQ + q0) * NH + h) * HDIM;
#pragma unroll
    for (int i = 0; i < 4; i++) {
        float4 r = make_float4(acc[i][0], acc[i][1], acc[i][2], acc[i][3]);
        *(float4*)(Ob + (size_t)(ty * 4 + i) * DIM + tx * 4) = r;
    }
}

// ---------------------------------------------------------------------------
// x = LayerNorm(x + a) * g + b     (in place on x). grid = MROWS, 256 thr.
// ---------------------------------------------------------------------------
__global__ __launch_bounds__(256)
void add_ln_kernel(float* __restrict__ x, const float* __restrict__ a,
                   const float* __restrict__ g, const float* __restrict__ b)
{
    __shared__ float red[9];
    size_t base = (size_t)blockIdx.x * DIM;
    int tid = threadIdx.x;

    float v[4];
    float s = 0.f;
#pragma unroll
    for (int i = 0; i < 4; i++) {
        int c = tid + i * 256;
        v[i] = x[base + c] + a[base + c];
        s += v[i];
    }
    for (int o = 16; o; o >>= 1) s += __shfl_xor_sync(0xffffffffu, s, o);
    if ((tid & 31) == 0) red[tid >> 5] = s;
    __syncthreads();
    if (tid == 0) {
        float t = 0.f;
        for (int w = 0; w < 8; w++) t += red[w];
        red[8] = t * (1.0f / DIM);
    }
    __syncthreads();
    float mean = red[8];

    float vs = 0.f;
#pragma unroll
    for (int i = 0; i < 4; i++) { float d = v[i] - mean; vs += d * d; }
    for (int o = 16; o; o >>= 1) vs += __shfl_xor_sync(0xffffffffu, vs, o);
    __syncthreads();
    if ((tid & 31) == 0) red[tid >> 5] = vs;
    __syncthreads();
    if (tid == 0) {
        float t = 0.f;
        for (int w = 0; w < 8; w++) t += red[w];
        red[8] = t * (1.0f / DIM);
    }
    __syncthreads();
    float inv = rsqrtf(red[8] + 1e-5f);

#pragma unroll
    for (int i = 0; i < 4; i++) {
        int c = tid + i * 256;
        x[base + c] = (v[i] - mean) * inv * g[c] + b[c];
    }
}

// ---------------------------------------------------------------------------
// Host-side orchestration
// ---------------------------------------------------------------------------
static inline void gemm(const float* A, const float* B, const float* bias,
                        float* C, int M, int N, int K, int relu)
{
    dim3 grid(N / 128, M / 128);
    sgemm_kernel<<<grid, 256>>>(A, B, bias, C, M, N, K, relu);
}

// Full attention sublayer: output (pre-LN) into t.  q/k/v/sc are scratch.
static void attention(const float* Xq, const float* Xkv,
                      const float* W, const float* Bb,
                      const int* tok, int causal,
                      float* q, float* k, float* v, float* t, float* sc)
{
    const size_t DD = (size_t)DIM * DIM;
    gemm(Xq,  W,          Bb,           q, MROWS, DIM, DIM, 0);
    gemm(Xkv, W + DD,     Bb + DIM,     k, MROWS, DIM, DIM, 0);
    gemm(Xkv, W + 2 * DD, Bb + 2 * DIM, v, MROWS, DIM, DIM, 0);
    attn_scores_kernel<<<dim3(SEQ / 64, SEQ / 64, BATCH * NH), 256>>>(q, k, tok, sc, causal);
    softmax_kernel<<<BATCH * NH * SEQ, 256>>>(sc);
    attn_av_kernel<<<dim3(1, SEQ / 64, BATCH * NH), 256>>>(sc, v, q);  // q reused as output
    gemm(q, W + 3 * DD, Bb + 3 * DIM, t, MROWS, DIM, DIM, 0);
}

extern "C" void kernel_launch(void* const* d_in, const int* in_sizes, int n_in,
                              void* d_out, int out_size)
{
    (void)in_sizes; (void)n_in; (void)out_size;

    const int*   src        = (const int*)  d_in[0];
    const int*   trg        = (const int*)  d_in[1];
    const float* src_emb    = (const float*)d_in[2];
    const float* trg_emb    = (const float*)d_in[3];
    const float* enc_attn_w = (const float*)d_in[4];
    const float* enc_attn_b = (const float*)d_in[5];
    const float* enc_ff1_w  = (const float*)d_in[6];
    const float* enc_ff1_b  = (const float*)d_in[7];
    const float* enc_ff2_w  = (const float*)d_in[8];
    const float* enc_ff2_b  = (const float*)d_in[9];
    const float* enc_ln_g   = (const float*)d_in[10];
    const float* enc_ln_b   = (const float*)d_in[11];
    const float* dec_self_w = (const float*)d_in[12];
    const float* dec_self_b = (const float*)d_in[13];
    const float* dec_cross_w= (const float*)d_in[14];
    const float* dec_cross_b= (const float*)d_in[15];
    const float* dec_ff1_w  = (const float*)d_in[16];
    const float* dec_ff1_b  = (const float*)d_in[17];
    const float* dec_ff2_w  = (const float*)d_in[18];
    const float* dec_ff2_b  = (const float*)d_in[19];
    const float* dec_ln_g   = (const float*)d_in[20];
    const float* dec_ln_b   = (const float*)d_in[21];
    const float* out_w      = (const float*)d_in[22];
    const float* out_b      = (const float*)d_in[23];
    float* out = (float*)d_out;

    float *x, *y, *q, *k, *v, *t, *ff, *sc;
    cudaGetSymbolAddress((void**)&x,  g_x);
    cudaGetSymbolAddress((void**)&y,  g_y);
    cudaGetSymbolAddress((void**)&q,  g_q);
    cudaGetSymbolAddress((void**)&k,  g_k);
    cudaGetSymbolAddress((void**)&v,  g_v);
    cudaGetSymbolAddress((void**)&t,  g_t);
    cudaGetSymbolAddress((void**)&ff, g_ff);
    cudaGetSymbolAddress((void**)&sc, g_sc);

    const size_t DD = (size_t)DIM * DIM;

    // -------------------- encoder --------------------
    embed_kernel<<<MROWS, 256>>>(src, src_emb, x);
    for (int l = 0; l < NL; l++) {
        attention(x, x, enc_attn_w + (size_t)l * 4 * DD, enc_attn_b + (size_t)l * 4 * DIM,
                  src, /*causal=*/0, q, k, v, t, sc);
        add_ln_kernel<<<MROWS, 256>>>(x, t,
            enc_ln_g + (size_t)(l * 2 + 0) * DIM, enc_ln_b + (size_t)(l * 2 + 0) * DIM);

        gemm(x,  enc_ff1_w + (size_t)l * DIM * FFD, enc_ff1_b + (size_t)l * FFD, ff,
             MROWS, FFD, DIM, 1);
        gemm(ff, enc_ff2_w + (size_t)l * FFD * DIM, enc_ff2_b + (size_t)l * DIM, t,
             MROWS, DIM, FFD, 0);
        add_ln_kernel<<<MROWS, 256>>>(x, t,
            enc_ln_g + (size_t)(l * 2 + 1) * DIM, enc_ln_b + (size_t)(l * 2 + 1) * DIM);
    }

    // -------------------- decoder --------------------
    embed_kernel<<<MROWS, 256>>>(trg, trg_emb, y);
    for (int l = 0; l < NL; l++) {
        // masked self-attention
        attention(y, y, dec_self_w + (size_t)l * 4 * DD, dec_self_b + (size_t)l * 4 * DIM,
                  trg, /*causal=*/1, q, k, v, t, sc);
        add_ln_kernel<<<MROWS, 256>>>(y, t,
            dec_ln_g + (size_t)(l * 3 + 0) * DIM, dec_ln_b + (size_t)(l * 3 + 0) * DIM);

        // cross-attention (K/V from encoder output x)
        attention(y, x, dec_cross_w + (size_t)l * 4 * DD, dec_cross_b + (size_t)l * 4 * DIM,
                  src, /*causal=*/0, q, k, v, t, sc);
        add_ln_kernel<<<MROWS, 256>>>(y, t,
            dec_ln_g + (size_t)(l * 3 + 1) * DIM, dec_ln_b + (size_t)(l * 3 + 1) * DIM);

        // feed-forward
        gemm(y,  dec_ff1_w + (size_t)l * DIM * FFD, dec_ff1_b + (size_t)l * FFD, ff,
             MROWS, FFD, DIM, 1);
        gemm(ff, dec_ff2_w + (size_t)l * FFD * DIM, dec_ff2_b + (size_t)l * DIM, t,
             MROWS, DIM, FFD, 0);
        add_ln_kernel<<<MROWS, 256>>>(y, t,
            dec_ln_g + (size_t)(l * 3 + 2) * DIM, dec_ln_b + (size_t)(l * 3 + 2) * DIM);
    }

    // -------------------- output projection --------------------
    gemm(y, out_w, out_b, out, MROWS, VOCAB, DIM, 0);
}